// round 16
// baseline (speedup 1.0000x reference)
#include <cuda_runtime.h>
#include <cuda_fp16.h>
#include <cstdint>
#include <math.h>

// Problem constants
#define CB 2
#define CS 2048
#define CD 1024
#define CH 16
#define CDK 64
#define CM (CB*CS)   // 4096 rows

// fp16 scratch (device globals: allocation-free rule). 64MB total.
__device__ __half h_in_q[CB*CS*CD];
__device__ __half h_in_k[CB*CS*CD];
__device__ __half h_in_v[CB*CS*CD];
__device__ __half h_wq[CD*CD];
__device__ __half h_wk[CD*CD];
__device__ __half h_wv[CD*CD];
__device__ __half h_wo[CD*CD];
__device__ __half h_q[CB*CS*CD];
__device__ __half h_k[CB*CS*CD];
__device__ __half h_vt[CB*CS*CD];   // Vt: [h*64+d][b*2048+s]
__device__ __half h_ao[CB*CS*CD];

// ---------------------------------------------------------------------------
// Helpers
// ---------------------------------------------------------------------------
__device__ __forceinline__ uint32_t smem_u32(const void* p) {
    uint32_t a;
    asm("{ .reg .u64 t; cvta.to.shared.u64 t, %1; cvt.u32.u64 %0, t; }" : "=r"(a) : "l"(p));
    return a;
}
__device__ __forceinline__ void cp_async16(uint32_t dst, const void* src) {
    asm volatile("cp.async.cg.shared.global [%0], [%1], 16;" :: "r"(dst), "l"(src) : "memory");
}
#define CP_COMMIT() asm volatile("cp.async.commit_group;" ::: "memory")
#define CP_WAIT(n)  asm volatile("cp.async.wait_group %0;" :: "n"(n) : "memory")

__device__ __forceinline__ void mma_f16(float c[4], const uint32_t a[4], const uint32_t b[2]) {
    asm volatile("mma.sync.aligned.m16n8k16.row.col.f32.f16.f16.f32 "
                 "{%0,%1,%2,%3}, {%4,%5,%6,%7}, {%8,%9}, {%0,%1,%2,%3};"
                 : "+f"(c[0]), "+f"(c[1]), "+f"(c[2]), "+f"(c[3])
                 : "r"(a[0]), "r"(a[1]), "r"(a[2]), "r"(a[3]), "r"(b[0]), "r"(b[1]));
}
__device__ __forceinline__ void ldsm_x4(uint32_t& r0, uint32_t& r1,
                                        uint32_t& r2, uint32_t& r3, uint32_t a) {
    asm volatile("ldmatrix.sync.aligned.m8n8.x4.shared.b16 {%0,%1,%2,%3}, [%4];"
                 : "=r"(r0), "=r"(r1), "=r"(r2), "=r"(r3) : "r"(a));
}
__device__ __forceinline__ uint32_t pack_h2(float x, float y) {
    __half2 h = __floats2half2_rn(x, y);
    return *(uint32_t*)&h;
}

// Single dynamic smem symbol shared by both kernels.
extern __shared__ char dynsmem[];

// ---------------------------------------------------------------------------
// fp32 -> fp16 conversion prepass (4 x float4 per thread for MLP)
// ---------------------------------------------------------------------------
__global__ void __launch_bounds__(256) cvt16(const float* __restrict__ in,
                                             __half* __restrict__ out, int n4)
{
    int base = (blockIdx.x * 256 + threadIdx.x) * 4;
    float4 v[4];
    #pragma unroll
    for (int j = 0; j < 4; j++)
        if (base + j < n4) v[j] = ((const float4*)in)[base + j];
    #pragma unroll
    for (int j = 0; j < 4; j++)
        if (base + j < n4) {
            ((__half2*)out)[2 * (base + j)]     = __floats2half2_rn(v[j].x, v[j].y);
            ((__half2*)out)[2 * (base + j) + 1] = __floats2half2_rn(v[j].z, v[j].w);
        }
}

// ---------------------------------------------------------------------------
// FP16 tensor-core GEMM: C[M,N] = A[M,K] * B[N,K]^T  (fp16 in, fp32 accum)
// CTA tile 128x256, BK=64 halves, 256 threads (8 warps 2Mx4N, 64x64 warp
// tiles). 2-stage cp.async, decoupled prefetch. Grid (4,32)=128 CTAs.
// MODE 0: fp16 out; MODE 1: fp16 out transposed (C_t[n][m]); MODE 2: fp32 out.
// ---------------------------------------------------------------------------
#define BM 128
#define BN 256
#define BKH 64
#define KSH 72                     // 64 + 8 pad halves; 144B rows
#define AWB (BM * KSH * 2)         // 18432 B per A stage
#define BWB (BN * KSH * 2)         // 36864 B per B stage
#define STGB (AWB + BWB)           // 55296 B per stage
#define GSMEMH (2 * STGB)          // 110592 B

template<int MODE>
__global__ void __launch_bounds__(256, 1) gemm_h(const __half* __restrict__ A,
                                                 const __half* __restrict__ B,
                                                 void* __restrict__ Cv,
                                                 int M, int N, int K)
{
    const int tid  = threadIdx.x;
    const int wid  = tid >> 5;
    const int lane = tid & 31;
    const int g    = lane >> 2;
    const int t    = lane & 3;
    const int wm   = wid >> 2;    // 0..1
    const int wn   = wid & 3;     // 0..3
    const int row0 = blockIdx.y * BM;
    const int col0 = blockIdx.x * BN;

    const int al_row = ((lane >> 3) & 1) * 8 + (lane & 7);
    const int al_col = ((lane >> 4) & 1) * 8;
    const int bl_row = ((lane >> 4) & 1) * 8 + (lane & 7);
    const int bl_col = ((lane >> 3) & 1) * 8;

    const __half* Ab = A + (size_t)row0 * K;
    const __half* Bb = B + (size_t)col0 * K;

    float acc[4][8][4];
    #pragma unroll
    for (int i = 0; i < 4; i++)
        #pragma unroll
        for (int j = 0; j < 8; j++)
            #pragma unroll
            for (int r = 0; r < 4; r++) acc[i][j][r] = 0.f;

    const int lr = tid >> 3;          // 0..31
    const int lc = (tid & 7) * 8;     // halves
    const uint32_t s0 = smem_u32(dynsmem);

    auto load_tile = [&](int kc, int s) {
        const __half* ag = Ab + kc * BKH;
        const __half* bg = Bb + kc * BKH;
        const uint32_t abase = s0 + s * STGB;
        const uint32_t bbase = abase + AWB;
        #pragma unroll
        for (int i = 0; i < 4; i++) {
            const int r = lr + i * 32;
            cp_async16(abase + r * (KSH * 2) + lc * 2, ag + (size_t)r * K + lc);
        }
        #pragma unroll
        for (int i = 0; i < 8; i++) {
            const int r = lr + i * 32;
            cp_async16(bbase + r * (KSH * 2) + lc * 2, bg + (size_t)r * K + lc);
        }
        CP_COMMIT();
    };

    const int NCH = K / BKH;   // 16
    load_tile(0, 0);
    int buf = 0;

    for (int kc = 0; kc < NCH; kc++) {
        if (kc + 1 < NCH) {
            load_tile(kc + 1, buf ^ 1);
            CP_WAIT(1);
        } else {
            CP_WAIT(0);
        }
        __syncthreads();

        const uint32_t Ac = s0 + buf * STGB;
        const uint32_t Bc = Ac + AWB;

        #pragma unroll
        for (int ks = 0; ks < 4; ks++) {
            const int kb = ks * 16;
            uint32_t af[4][4], bf[8][2];
            const uint32_t aa = Ac + ((wm * 64 + al_row) * KSH + kb + al_col) * 2;
            #pragma unroll
            for (int i = 0; i < 4; i++)
                ldsm_x4(af[i][0], af[i][1], af[i][2], af[i][3],
                        aa + i * (16 * KSH * 2));
            const uint32_t ba = Bc + ((wn * 64 + bl_row) * KSH + kb + bl_col) * 2;
            #pragma unroll
            for (int jp = 0; jp < 4; jp++)
                ldsm_x4(bf[2 * jp][0], bf[2 * jp][1],
                        bf[2 * jp + 1][0], bf[2 * jp + 1][1],
                        ba + jp * (16 * KSH * 2));
            #pragma unroll
            for (int i = 0; i < 4; i++)
                #pragma unroll
                for (int j = 0; j < 8; j++)
                    mma_f16(acc[i][j], af[i], bf[j]);
        }
        __syncthreads();
        buf ^= 1;
    }

    #pragma unroll
    for (int i = 0; i < 4; i++) {
        #pragma unroll
        for (int j = 0; j < 8; j++) {
            const int m = row0 + wm * 64 + i * 16 + g;
            const int n = col0 + wn * 64 + j * 8 + 2 * t;
            if (MODE == 2) {
                float* C = (float*)Cv;
                *(float2*)&C[(size_t)m * N + n]       = make_float2(acc[i][j][0], acc[i][j][1]);
                *(float2*)&C[(size_t)(m + 8) * N + n] = make_float2(acc[i][j][2], acc[i][j][3]);
            } else if (MODE == 1) {
                __half* C = (__half*)Cv;
                C[(size_t)n * M + m]           = __float2half_rn(acc[i][j][0]);
                C[(size_t)(n + 1) * M + m]     = __float2half_rn(acc[i][j][1]);
                C[(size_t)n * M + m + 8]       = __float2half_rn(acc[i][j][2]);
                C[(size_t)(n + 1) * M + m + 8] = __float2half_rn(acc[i][j][3]);
            } else {
                __half* C = (__half*)Cv;
                *(uint32_t*)&C[(size_t)m * N + n]       = pack_h2(acc[i][j][0], acc[i][j][1]);
                *(uint32_t*)&C[(size_t)(m + 8) * N + n] = pack_h2(acc[i][j][2], acc[i][j][3]);
            }
        }
    }
}

// ---------------------------------------------------------------------------
// FP16 tensor-core causal flash attention v9.
// As v8 but NO P smem round-trip: the m16n8 C-fragment of S maps exactly
// onto m16n8k16 A-fragment halves (a0=s[2kc][0,1], a1=s[2kc][2,3],
// a2=s[2kc+1][0,1], a3=s[2kc+1][2,3]) -> P stays in registers.
// Smem: K[2][64][72] + Vt[64][72] = 27.6KB.
// ---------------------------------------------------------------------------
#define KSTH 72
#define KT  64
#define QT  64
#define KSTGB (KT * KSTH * 2)            // 9216 B per K stage
#define AOFF_V (2 * KSTGB)               // 18432
#define ASMEMH (AOFF_V + KT * KSTH * 2)  // 27648 B

__global__ void __launch_bounds__(128, 3) attn_tc(const __half* __restrict__ qg,
                                                  const __half* __restrict__ kg,
                                                  const __half* __restrict__ vtg,
                                                  __half* __restrict__ og)
{
    const int bh = blockIdx.y;
    const int b  = bh >> 4;
    const int h  = bh & 15;
    const int q0 = (gridDim.x - 1 - blockIdx.x) * QT;   // longest CTAs first
    const int tid = threadIdx.x;
    const int w = tid >> 5, lane = tid & 31;
    const int g = lane >> 2, t = lane & 3;

    const int bl_row = ((lane >> 4) & 1) * 8 + (lane & 7);
    const int bl_col = ((lane >> 3) & 1) * 8;

    const __half* kbase  = kg + ((size_t)(b * CS)) * CD + h * CDK;
    const __half* vtbase = vtg + ((size_t)(h * CDK)) * CM + (size_t)b * CS;

    // Q fragments (fp16, pre-scaled by log2(e)/8 -> exp2-domain softmax)
    const float QSCALE = 0.125f * 1.4426950408889634f;
    const __half* qbase = qg + ((size_t)(b * CS + q0)) * CD + h * CDK;
    uint32_t qf[4][4];
    {
        const __half* qr0 = qbase + (size_t)(16 * w + g) * CD;
        const __half* qr1 = qbase + (size_t)(16 * w + g + 8) * CD;
        #pragma unroll
        for (int kc = 0; kc < 4; kc++) {
            #pragma unroll
            for (int half8 = 0; half8 < 2; half8++) {
                int c0 = 16 * kc + 8 * half8 + 2 * t;
                float2 f0 = __half22float2(*(const __half2*)(qr0 + c0));
                float2 f1 = __half22float2(*(const __half2*)(qr1 + c0));
                qf[kc][2 * half8]     = pack_h2(f0.x * QSCALE, f0.y * QSCALE);
                qf[kc][2 * half8 + 1] = pack_h2(f1.x * QSCALE, f1.y * QSCALE);
            }
        }
    }

    const uint32_t sb = smem_u32(dynsmem);
    const uint32_t vb0 = sb + AOFF_V;

    auto load_K = [&](int kt_, int s) {
        const int k0 = kt_ * KT;
        const uint32_t kd = sb + s * KSTGB;
        #pragma unroll
        for (int i = 0; i < 4; i++) {
            int idx = tid + i * 128;
            int r = idx >> 3, c = idx & 7;
            cp_async16(kd + r * (KSTH * 2) + c * 16, kbase + (size_t)(k0 + r) * CD + c * 8);
        }
        CP_COMMIT();
    };
    auto load_V = [&](int kt_) {
        const int k0 = kt_ * KT;
        #pragma unroll
        for (int i = 0; i < 4; i++) {
            int idx = tid + i * 128;
            int r = idx >> 3, c = idx & 7;
            cp_async16(vb0 + r * (KSTH * 2) + c * 16, vtbase + (size_t)r * CM + k0 + c * 8);
        }
        CP_COMMIT();
    };

    float o[8][4];
    #pragma unroll
    for (int nt = 0; nt < 8; nt++)
        #pragma unroll
        for (int c = 0; c < 4; c++) o[nt][c] = 0.f;
    float mrow[2] = {-1e30f, -1e30f};
    float lrow[2] = {0.f, 0.f};

    const int ntiles = q0 / KT + 1;
    int buf = 0;
    load_K(0, 0);
    load_V(0);

    for (int kt = 0; kt < ntiles; kt++) {
        const int k0 = kt * KT;
        if (kt + 1 < ntiles) {
            load_K(kt + 1, buf ^ 1);
            CP_WAIT(1);            // K(kt) and V(kt) complete
        } else {
            CP_WAIT(0);
        }
        __syncthreads();

        if (k0 <= q0 + 16 * w + 15) {
            const uint32_t Kb = sb + buf * KSTGB;

            // S = Q * K^T (fp16, k16 steps)
            float s[8][4];
            #pragma unroll
            for (int nt = 0; nt < 8; nt++)
                #pragma unroll
                for (int c = 0; c < 4; c++) s[nt][c] = 0.f;

            #pragma unroll
            for (int kc = 0; kc < 4; kc++) {
                uint32_t bf[8][2];
                const uint32_t ka = Kb + (bl_row * KSTH + 16 * kc + bl_col) * 2;
                #pragma unroll
                for (int jp = 0; jp < 4; jp++)
                    ldsm_x4(bf[2 * jp][0], bf[2 * jp][1],
                            bf[2 * jp + 1][0], bf[2 * jp + 1][1],
                            ka + jp * (16 * KSTH * 2));
                #pragma unroll
                for (int nt = 0; nt < 8; nt++)
                    mma_f16(s[nt], qf[kc], bf[nt]);
            }

            // causal mask (diagonal tiles only; scale folded into Q)
            const bool needmask = (k0 + KT - 1) > (q0 + 16 * w);
            if (needmask) {
                #pragma unroll
                for (int nt = 0; nt < 8; nt++)
                    #pragma unroll
                    for (int c = 0; c < 4; c++) {
                        int key = k0 + 8 * nt + 2 * t + (c & 1);
                        int qr  = q0 + 16 * w + 8 * (c >> 1) + g;
                        if (key > qr) s[nt][c] = -1e30f;
                    }
            }

            // online softmax in exp2 domain
            #pragma unroll
            for (int p = 0; p < 2; p++) {
                float mx = -1e30f;
                #pragma unroll
                for (int nt = 0; nt < 8; nt++) {
                    mx = fmaxf(mx, s[nt][2 * p]);
                    mx = fmaxf(mx, s[nt][2 * p + 1]);
                }
                mx = fmaxf(mx, __shfl_xor_sync(0xffffffffu, mx, 1));
                mx = fmaxf(mx, __shfl_xor_sync(0xffffffffu, mx, 2));
                const float mnew = fmaxf(mrow[p], mx);
                const float corr = exp2f(mrow[p] - mnew);
                mrow[p] = mnew;
                float ls = 0.f;
                #pragma unroll
                for (int nt = 0; nt < 8; nt++) {
                    float p0 = exp2f(s[nt][2 * p]     - mnew);
                    float p1 = exp2f(s[nt][2 * p + 1] - mnew);
                    s[nt][2 * p]     = p0;
                    s[nt][2 * p + 1] = p1;
                    ls += p0 + p1;
                }
                #pragma unroll
                for (int nt = 0; nt < 8; nt++) {
                    o[nt][2 * p]     *= corr;
                    o[nt][2 * p + 1] *= corr;
                }
                lrow[p] = lrow[p] * corr + ls;
            }

            // O += P * V : P直接 in registers (C-frag == A-frag halves)
            #pragma unroll
            for (int kc = 0; kc < 4; kc++) {
                uint32_t af[4];
                af[0] = pack_h2(s[2 * kc][0],     s[2 * kc][1]);
                af[1] = pack_h2(s[2 * kc][2],     s[2 * kc][3]);
                af[2] = pack_h2(s[2 * kc + 1][0], s[2 * kc + 1][1]);
                af[3] = pack_h2(s[2 * kc + 1][2], s[2 * kc + 1][3]);
                uint32_t bf[8][2];
                const uint32_t va = vb0 + (bl_row * KSTH + 16 * kc + bl_col) * 2;
                #pragma unroll
                for (int jp = 0; jp < 4; jp++)
                    ldsm_x4(bf[2 * jp][0], bf[2 * jp][1],
                            bf[2 * jp + 1][0], bf[2 * jp + 1][1],
                            va + jp * (16 * KSTH * 2));
                #pragma unroll
                for (int nt = 0; nt < 8; nt++)
                    mma_f16(o[nt], af, bf[nt]);
            }
        }
        __syncthreads();           // all warps done with V(kt)
        if (kt + 1 < ntiles) load_V(kt + 1);
        buf ^= 1;
    }

    // finalize
    float inv[2];
    #pragma unroll
    for (int p = 0; p < 2; p++) {
        float lr = lrow[p];
        lr += __shfl_xor_sync(0xffffffffu, lr, 1);
        lr += __shfl_xor_sync(0xffffffffu, lr, 2);
        inv[p] = 1.f / lr;
    }

    __half* obase = og + ((size_t)(b * CS + q0)) * CD + h * CDK;
    #pragma unroll
    for (int nt = 0; nt < 8; nt++) {
        const int r0 = 16 * w + g;
        *(uint32_t*)(obase + (size_t)r0 * CD + 8 * nt + 2 * t) =
            pack_h2(o[nt][0] * inv[0], o[nt][1] * inv[0]);
        *(uint32_t*)(obase + (size_t)(r0 + 8) * CD + 8 * nt + 2 * t) =
            pack_h2(o[nt][2] * inv[1], o[nt][3] * inv[1]);
    }
}

// ---------------------------------------------------------------------------
// Launch. Inputs: Q, K, V, mask(ignored), w_q, w_k, w_v, w_o. Out: [B,S,D] f32
// ---------------------------------------------------------------------------
extern "C" void kernel_launch(void* const* d_in, const int* in_sizes, int n_in,
                              void* d_out, int out_size)
{
    const float* Q  = (const float*)d_in[0];
    const float* K  = (const float*)d_in[1];
    const float* V  = (const float*)d_in[2];
    const float* wq = (const float*)d_in[4];
    const float* wk = (const float*)d_in[5];
    const float* wv = (const float*)d_in[6];
    const float* wo = (const float*)d_in[7];
    float* out = (float*)d_out;

    __half *hiq, *hik, *hiv, *hwq, *hwk, *hwv, *hwo, *hq, *hk, *hvt, *hao;
    cudaGetSymbolAddress((void**)&hiq, h_in_q);
    cudaGetSymbolAddress((void**)&hik, h_in_k);
    cudaGetSymbolAddress((void**)&hiv, h_in_v);
    cudaGetSymbolAddress((void**)&hwq, h_wq);
    cudaGetSymbolAddress((void**)&hwk, h_wk);
    cudaGetSymbolAddress((void**)&hwv, h_wv);
    cudaGetSymbolAddress((void**)&hwo, h_wo);
    cudaGetSymbolAddress((void**)&hq,  h_q);
    cudaGetSymbolAddress((void**)&hk,  h_k);
    cudaGetSymbolAddress((void**)&hvt, h_vt);
    cudaGetSymbolAddress((void**)&hao, h_ao);

    cudaFuncSetAttribute(gemm_h<0>, cudaFuncAttributeMaxDynamicSharedMemorySize, GSMEMH);
    cudaFuncSetAttribute(gemm_h<1>, cudaFuncAttributeMaxDynamicSharedMemorySize, GSMEMH);
    cudaFuncSetAttribute(gemm_h<2>, cudaFuncAttributeMaxDynamicSharedMemorySize, GSMEMH);
    cudaFuncSetAttribute(attn_tc, cudaFuncAttributeMaxDynamicSharedMemorySize, ASMEMH);

    const int NT4 = CB * CS * CD / 4;   // 1048576
    const int NW4 = CD * CD / 4;        // 262144
    cvt16<<<NT4 / 1024, 256>>>(Q, hiq, NT4);
    cvt16<<<NT4 / 1024, 256>>>(K, hik, NT4);
    cvt16<<<NT4 / 1024, 256>>>(V, hiv, NT4);
    cvt16<<<NW4 / 1024, 256>>>(wq, hwq, NW4);
    cvt16<<<NW4 / 1024, 256>>>(wk, hwk, NW4);
    cvt16<<<NW4 / 1024, 256>>>(wv, hwv, NW4);
    cvt16<<<NW4 / 1024, 256>>>(wo, hwo, NW4);

    dim3 gg(CD / BN, CM / BM);   // (4, 32) = 128 CTAs, single wave
    gemm_h<0><<<gg, 256, GSMEMH>>>(hiq, hwq, hq,  CM, CD, CD);
    gemm_h<0><<<gg, 256, GSMEMH>>>(hik, hwk, hk,  CM, CD, CD);
    gemm_h<1><<<gg, 256, GSMEMH>>>(hiv, hwv, hvt, CM, CD, CD);   // writes Vt

    attn_tc<<<dim3(CS / QT, CB * CH), 128, ASMEMH>>>(hq, hk, hvt, hao);

    gemm_h<2><<<gg, 256, GSMEMH>>>(hao, hwo, out, CM, CD, CD);
}

// round 17
// speedup vs baseline: 1.1202x; 1.1202x over previous
#include <cuda_runtime.h>
#include <cuda_fp16.h>
#include <cstdint>
#include <math.h>

// Problem constants
#define CB 2
#define CS 2048
#define CD 1024
#define CH 16
#define CDK 64
#define CM (CB*CS)   // 4096 rows

// fp16 scratch (device globals: allocation-free rule). 64MB total.
__device__ __half h_in_q[CB*CS*CD];
__device__ __half h_in_k[CB*CS*CD];
__device__ __half h_in_v[CB*CS*CD];
__device__ __half h_wq[CD*CD];
__device__ __half h_wk[CD*CD];
__device__ __half h_wv[CD*CD];
__device__ __half h_wo[CD*CD];
__device__ __half h_q[CB*CS*CD];
__device__ __half h_k[CB*CS*CD];
__device__ __half h_vt[CB*CS*CD];   // Vt: [h*64+d][b*2048+s]
__device__ __half h_ao[CB*CS*CD];

// ---------------------------------------------------------------------------
// Helpers
// ---------------------------------------------------------------------------
__device__ __forceinline__ uint32_t smem_u32(const void* p) {
    uint32_t a;
    asm("{ .reg .u64 t; cvta.to.shared.u64 t, %1; cvt.u32.u64 %0, t; }" : "=r"(a) : "l"(p));
    return a;
}
__device__ __forceinline__ void cp_async16(uint32_t dst, const void* src) {
    asm volatile("cp.async.cg.shared.global [%0], [%1], 16;" :: "r"(dst), "l"(src) : "memory");
}
#define CP_COMMIT() asm volatile("cp.async.commit_group;" ::: "memory")
#define CP_WAIT(n)  asm volatile("cp.async.wait_group %0;" :: "n"(n) : "memory")

__device__ __forceinline__ void mma_f16(float c[4], const uint32_t a[4], const uint32_t b[2]) {
    asm volatile("mma.sync.aligned.m16n8k16.row.col.f32.f16.f16.f32 "
                 "{%0,%1,%2,%3}, {%4,%5,%6,%7}, {%8,%9}, {%0,%1,%2,%3};"
                 : "+f"(c[0]), "+f"(c[1]), "+f"(c[2]), "+f"(c[3])
                 : "r"(a[0]), "r"(a[1]), "r"(a[2]), "r"(a[3]), "r"(b[0]), "r"(b[1]));
}
__device__ __forceinline__ void ldsm_x4(uint32_t& r0, uint32_t& r1,
                                        uint32_t& r2, uint32_t& r3, uint32_t a) {
    asm volatile("ldmatrix.sync.aligned.m8n8.x4.shared.b16 {%0,%1,%2,%3}, [%4];"
                 : "=r"(r0), "=r"(r1), "=r"(r2), "=r"(r3) : "r"(a));
}
__device__ __forceinline__ uint32_t pack_h2(float x, float y) {
    __half2 h = __floats2half2_rn(x, y);
    return *(uint32_t*)&h;
}

// Single dynamic smem symbol shared by both kernels.
extern __shared__ char dynsmem[];

// ---------------------------------------------------------------------------
// fp32 -> fp16 conversion prepass.
// cvt3: Q,K,V activations (grid.y selects buffer). cvt4: 4 weight matrices.
// One float4 per thread (R15-measured-best shape: high occupancy, MLP-lite).
// ---------------------------------------------------------------------------
__global__ void __launch_bounds__(256) cvt3(const float* __restrict__ q,
                                            const float* __restrict__ k,
                                            const float* __restrict__ v,
                                            __half* __restrict__ oq,
                                            __half* __restrict__ ok,
                                            __half* __restrict__ ov)
{
    const float* in  = (blockIdx.y == 0) ? q : (blockIdx.y == 1) ? k : v;
    __half*      out = (blockIdx.y == 0) ? oq : (blockIdx.y == 1) ? ok : ov;
    int i = blockIdx.x * 256 + threadIdx.x;
    float4 val = ((const float4*)in)[i];
    ((__half2*)out)[2 * i]     = __floats2half2_rn(val.x, val.y);
    ((__half2*)out)[2 * i + 1] = __floats2half2_rn(val.z, val.w);
}
__global__ void __launch_bounds__(256) cvt4(const float* __restrict__ a,
                                            const float* __restrict__ b,
                                            const float* __restrict__ c,
                                            const float* __restrict__ d,
                                            __half* __restrict__ oa,
                                            __half* __restrict__ ob,
                                            __half* __restrict__ oc,
                                            __half* __restrict__ od)
{
    const float* in  = (blockIdx.y == 0) ? a : (blockIdx.y == 1) ? b
                     : (blockIdx.y == 2) ? c : d;
    __half*      out = (blockIdx.y == 0) ? oa : (blockIdx.y == 1) ? ob
                     : (blockIdx.y == 2) ? oc : od;
    int i = blockIdx.x * 256 + threadIdx.x;
    float4 val = ((const float4*)in)[i];
    ((__half2*)out)[2 * i]     = __floats2half2_rn(val.x, val.y);
    ((__half2*)out)[2 * i + 1] = __floats2half2_rn(val.z, val.w);
}

// ---------------------------------------------------------------------------
// FP16 tensor-core GEMM: C[M,N] = A[M,K] * B[N,K]^T  (fp16 in, fp32 accum)
// CTA tile 128x256, BK=64 halves, 256 threads (8 warps 2Mx4N, 64x64 warp
// tiles). 2-stage cp.async, decoupled prefetch. Grid (4,32)=128 CTAs.
// MODE 0: fp16 out; MODE 1: fp16 out transposed (C_t[n][m]); MODE 2: fp32 out.
// ---------------------------------------------------------------------------
#define BM 128
#define BN 256
#define BKH 64
#define KSH 72                     // 64 + 8 pad halves; 144B rows
#define AWB (BM * KSH * 2)         // 18432 B per A stage
#define BWB (BN * KSH * 2)         // 36864 B per B stage
#define STGB (AWB + BWB)           // 55296 B per stage
#define GSMEMH (2 * STGB)          // 110592 B

template<int MODE>
__global__ void __launch_bounds__(256, 1) gemm_h(const __half* __restrict__ A,
                                                 const __half* __restrict__ B,
                                                 void* __restrict__ Cv,
                                                 int M, int N, int K)
{
    const int tid  = threadIdx.x;
    const int wid  = tid >> 5;
    const int lane = tid & 31;
    const int g    = lane >> 2;
    const int t    = lane & 3;
    const int wm   = wid >> 2;    // 0..1
    const int wn   = wid & 3;     // 0..3
    const int row0 = blockIdx.y * BM;
    const int col0 = blockIdx.x * BN;

    const int al_row = ((lane >> 3) & 1) * 8 + (lane & 7);
    const int al_col = ((lane >> 4) & 1) * 8;
    const int bl_row = ((lane >> 4) & 1) * 8 + (lane & 7);
    const int bl_col = ((lane >> 3) & 1) * 8;

    const __half* Ab = A + (size_t)row0 * K;
    const __half* Bb = B + (size_t)col0 * K;

    float acc[4][8][4];
    #pragma unroll
    for (int i = 0; i < 4; i++)
        #pragma unroll
        for (int j = 0; j < 8; j++)
            #pragma unroll
            for (int r = 0; r < 4; r++) acc[i][j][r] = 0.f;

    const int lr = tid >> 3;          // 0..31
    const int lc = (tid & 7) * 8;     // halves
    const uint32_t s0 = smem_u32(dynsmem);

    auto load_tile = [&](int kc, int s) {
        const __half* ag = Ab + kc * BKH;
        const __half* bg = Bb + kc * BKH;
        const uint32_t abase = s0 + s * STGB;
        const uint32_t bbase = abase + AWB;
        #pragma unroll
        for (int i = 0; i < 4; i++) {
            const int r = lr + i * 32;
            cp_async16(abase + r * (KSH * 2) + lc * 2, ag + (size_t)r * K + lc);
        }
        #pragma unroll
        for (int i = 0; i < 8; i++) {
            const int r = lr + i * 32;
            cp_async16(bbase + r * (KSH * 2) + lc * 2, bg + (size_t)r * K + lc);
        }
        CP_COMMIT();
    };

    const int NCH = K / BKH;   // 16
    load_tile(0, 0);
    int buf = 0;

    for (int kc = 0; kc < NCH; kc++) {
        if (kc + 1 < NCH) {
            load_tile(kc + 1, buf ^ 1);
            CP_WAIT(1);
        } else {
            CP_WAIT(0);
        }
        __syncthreads();

        const uint32_t Ac = s0 + buf * STGB;
        const uint32_t Bc = Ac + AWB;

        #pragma unroll
        for (int ks = 0; ks < 4; ks++) {
            const int kb = ks * 16;
            uint32_t af[4][4], bf[8][2];
            const uint32_t aa = Ac + ((wm * 64 + al_row) * KSH + kb + al_col) * 2;
            #pragma unroll
            for (int i = 0; i < 4; i++)
                ldsm_x4(af[i][0], af[i][1], af[i][2], af[i][3],
                        aa + i * (16 * KSH * 2));
            const uint32_t ba = Bc + ((wn * 64 + bl_row) * KSH + kb + bl_col) * 2;
            #pragma unroll
            for (int jp = 0; jp < 4; jp++)
                ldsm_x4(bf[2 * jp][0], bf[2 * jp][1],
                        bf[2 * jp + 1][0], bf[2 * jp + 1][1],
                        ba + jp * (16 * KSH * 2));
            #pragma unroll
            for (int i = 0; i < 4; i++)
                #pragma unroll
                for (int j = 0; j < 8; j++)
                    mma_f16(acc[i][j], af[i], bf[j]);
        }
        __syncthreads();
        buf ^= 1;
    }

    #pragma unroll
    for (int i = 0; i < 4; i++) {
        #pragma unroll
        for (int j = 0; j < 8; j++) {
            const int m = row0 + wm * 64 + i * 16 + g;
            const int n = col0 + wn * 64 + j * 8 + 2 * t;
            if (MODE == 2) {
                float* C = (float*)Cv;
                *(float2*)&C[(size_t)m * N + n]       = make_float2(acc[i][j][0], acc[i][j][1]);
                *(float2*)&C[(size_t)(m + 8) * N + n] = make_float2(acc[i][j][2], acc[i][j][3]);
            } else if (MODE == 1) {
                __half* C = (__half*)Cv;
                C[(size_t)n * M + m]           = __float2half_rn(acc[i][j][0]);
                C[(size_t)(n + 1) * M + m]     = __float2half_rn(acc[i][j][1]);
                C[(size_t)n * M + m + 8]       = __float2half_rn(acc[i][j][2]);
                C[(size_t)(n + 1) * M + m + 8] = __float2half_rn(acc[i][j][3]);
            } else {
                __half* C = (__half*)Cv;
                *(uint32_t*)&C[(size_t)m * N + n]       = pack_h2(acc[i][j][0], acc[i][j][1]);
                *(uint32_t*)&C[(size_t)(m + 8) * N + n] = pack_h2(acc[i][j][2], acc[i][j][3]);
            }
        }
    }
}

// ---------------------------------------------------------------------------
// FP16 tensor-core causal flash attention v9 (P in registers).
// 64q/CTA, Q in regs exp2-scaled, K 2-stage cp.async, Vt single-buffered,
// 3 CTAs/SM. C-frag of S == A-frag halves of PV -> no P smem round-trip.
// Smem: K[2][64][72] + Vt[64][72] = 27.6KB.
// ---------------------------------------------------------------------------
#define KSTH 72
#define KT  64
#define QT  64
#define KSTGB (KT * KSTH * 2)            // 9216 B per K stage
#define AOFF_V (2 * KSTGB)               // 18432
#define ASMEMH (AOFF_V + KT * KSTH * 2)  // 27648 B

__global__ void __launch_bounds__(128, 3) attn_tc(const __half* __restrict__ qg,
                                                  const __half* __restrict__ kg,
                                                  const __half* __restrict__ vtg,
                                                  __half* __restrict__ og)
{
    const int bh = blockIdx.y;
    const int b  = bh >> 4;
    const int h  = bh & 15;
    const int q0 = (gridDim.x - 1 - blockIdx.x) * QT;   // longest CTAs first
    const int tid = threadIdx.x;
    const int w = tid >> 5, lane = tid & 31;
    const int g = lane >> 2, t = lane & 3;

    const int bl_row = ((lane >> 4) & 1) * 8 + (lane & 7);
    const int bl_col = ((lane >> 3) & 1) * 8;

    const __half* kbase  = kg + ((size_t)(b * CS)) * CD + h * CDK;
    const __half* vtbase = vtg + ((size_t)(h * CDK)) * CM + (size_t)b * CS;

    // Q fragments (fp16, pre-scaled by log2(e)/8 -> exp2-domain softmax)
    const float QSCALE = 0.125f * 1.4426950408889634f;
    const __half* qbase = qg + ((size_t)(b * CS + q0)) * CD + h * CDK;
    uint32_t qf[4][4];
    {
        const __half* qr0 = qbase + (size_t)(16 * w + g) * CD;
        const __half* qr1 = qbase + (size_t)(16 * w + g + 8) * CD;
        #pragma unroll
        for (int kc = 0; kc < 4; kc++) {
            #pragma unroll
            for (int half8 = 0; half8 < 2; half8++) {
                int c0 = 16 * kc + 8 * half8 + 2 * t;
                float2 f0 = __half22float2(*(const __half2*)(qr0 + c0));
                float2 f1 = __half22float2(*(const __half2*)(qr1 + c0));
                qf[kc][2 * half8]     = pack_h2(f0.x * QSCALE, f0.y * QSCALE);
                qf[kc][2 * half8 + 1] = pack_h2(f1.x * QSCALE, f1.y * QSCALE);
            }
        }
    }

    const uint32_t sb = smem_u32(dynsmem);
    const uint32_t vb0 = sb + AOFF_V;

    auto load_K = [&](int kt_, int s) {
        const int k0 = kt_ * KT;
        const uint32_t kd = sb + s * KSTGB;
        #pragma unroll
        for (int i = 0; i < 4; i++) {
            int idx = tid + i * 128;
            int r = idx >> 3, c = idx & 7;
            cp_async16(kd + r * (KSTH * 2) + c * 16, kbase + (size_t)(k0 + r) * CD + c * 8);
        }
        CP_COMMIT();
    };
    auto load_V = [&](int kt_) {
        const int k0 = kt_ * KT;
        #pragma unroll
        for (int i = 0; i < 4; i++) {
            int idx = tid + i * 128;
            int r = idx >> 3, c = idx & 7;
            cp_async16(vb0 + r * (KSTH * 2) + c * 16, vtbase + (size_t)r * CM + k0 + c * 8);
        }
        CP_COMMIT();
    };

    float o[8][4];
    #pragma unroll
    for (int nt = 0; nt < 8; nt++)
        #pragma unroll
        for (int c = 0; c < 4; c++) o[nt][c] = 0.f;
    float mrow[2] = {-1e30f, -1e30f};
    float lrow[2] = {0.f, 0.f};

    const int ntiles = q0 / KT + 1;
    int buf = 0;
    load_K(0, 0);
    load_V(0);

    for (int kt = 0; kt < ntiles; kt++) {
        const int k0 = kt * KT;
        if (kt + 1 < ntiles) {
            load_K(kt + 1, buf ^ 1);
            CP_WAIT(1);            // K(kt) and V(kt) complete
        } else {
            CP_WAIT(0);
        }
        __syncthreads();

        if (k0 <= q0 + 16 * w + 15) {
            const uint32_t Kb = sb + buf * KSTGB;

            // S = Q * K^T (fp16, k16 steps)
            float s[8][4];
            #pragma unroll
            for (int nt = 0; nt < 8; nt++)
                #pragma unroll
                for (int c = 0; c < 4; c++) s[nt][c] = 0.f;

            #pragma unroll
            for (int kc = 0; kc < 4; kc++) {
                uint32_t bf[8][2];
                const uint32_t ka = Kb + (bl_row * KSTH + 16 * kc + bl_col) * 2;
                #pragma unroll
                for (int jp = 0; jp < 4; jp++)
                    ldsm_x4(bf[2 * jp][0], bf[2 * jp][1],
                            bf[2 * jp + 1][0], bf[2 * jp + 1][1],
                            ka + jp * (16 * KSTH * 2));
                #pragma unroll
                for (int nt = 0; nt < 8; nt++)
                    mma_f16(s[nt], qf[kc], bf[nt]);
            }

            // causal mask (diagonal tiles only; scale folded into Q)
            const bool needmask = (k0 + KT - 1) > (q0 + 16 * w);
            if (needmask) {
                #pragma unroll
                for (int nt = 0; nt < 8; nt++)
                    #pragma unroll
                    for (int c = 0; c < 4; c++) {
                        int key = k0 + 8 * nt + 2 * t + (c & 1);
                        int qr  = q0 + 16 * w + 8 * (c >> 1) + g;
                        if (key > qr) s[nt][c] = -1e30f;
                    }
            }

            // online softmax in exp2 domain
            #pragma unroll
            for (int p = 0; p < 2; p++) {
                float mx = -1e30f;
                #pragma unroll
                for (int nt = 0; nt < 8; nt++) {
                    mx = fmaxf(mx, s[nt][2 * p]);
                    mx = fmaxf(mx, s[nt][2 * p + 1]);
                }
                mx = fmaxf(mx, __shfl_xor_sync(0xffffffffu, mx, 1));
                mx = fmaxf(mx, __shfl_xor_sync(0xffffffffu, mx, 2));
                const float mnew = fmaxf(mrow[p], mx);
                const float corr = exp2f(mrow[p] - mnew);
                mrow[p] = mnew;
                float ls = 0.f;
                #pragma unroll
                for (int nt = 0; nt < 8; nt++) {
                    float p0 = exp2f(s[nt][2 * p]     - mnew);
                    float p1 = exp2f(s[nt][2 * p + 1] - mnew);
                    s[nt][2 * p]     = p0;
                    s[nt][2 * p + 1] = p1;
                    ls += p0 + p1;
                }
                #pragma unroll
                for (int nt = 0; nt < 8; nt++) {
                    o[nt][2 * p]     *= corr;
                    o[nt][2 * p + 1] *= corr;
                }
                lrow[p] = lrow[p] * corr + ls;
            }

            // O += P * V : P in registers (C-frag == A-frag halves)
            #pragma unroll
            for (int kc = 0; kc < 4; kc++) {
                uint32_t af[4];
                af[0] = pack_h2(s[2 * kc][0],     s[2 * kc][1]);
                af[1] = pack_h2(s[2 * kc][2],     s[2 * kc][3]);
                af[2] = pack_h2(s[2 * kc + 1][0], s[2 * kc + 1][1]);
                af[3] = pack_h2(s[2 * kc + 1][2], s[2 * kc + 1][3]);
                uint32_t bf[8][2];
                const uint32_t va = vb0 + (bl_row * KSTH + 16 * kc + bl_col) * 2;
                #pragma unroll
                for (int jp = 0; jp < 4; jp++)
                    ldsm_x4(bf[2 * jp][0], bf[2 * jp][1],
                            bf[2 * jp + 1][0], bf[2 * jp + 1][1],
                            va + jp * (16 * KSTH * 2));
                #pragma unroll
                for (int nt = 0; nt < 8; nt++)
                    mma_f16(o[nt], af, bf[nt]);
            }
        }
        __syncthreads();           // all warps done with V(kt)
        if (kt + 1 < ntiles) load_V(kt + 1);
        buf ^= 1;
    }

    // finalize
    float inv[2];
    #pragma unroll
    for (int p = 0; p < 2; p++) {
        float lr = lrow[p];
        lr += __shfl_xor_sync(0xffffffffu, lr, 1);
        lr += __shfl_xor_sync(0xffffffffu, lr, 2);
        inv[p] = 1.f / lr;
    }

    __half* obase = og + ((size_t)(b * CS + q0)) * CD + h * CDK;
    #pragma unroll
    for (int nt = 0; nt < 8; nt++) {
        const int r0 = 16 * w + g;
        *(uint32_t*)(obase + (size_t)r0 * CD + 8 * nt + 2 * t) =
            pack_h2(o[nt][0] * inv[0], o[nt][1] * inv[0]);
        *(uint32_t*)(obase + (size_t)(r0 + 8) * CD + 8 * nt + 2 * t) =
            pack_h2(o[nt][2] * inv[1], o[nt][3] * inv[1]);
    }
}

// ---------------------------------------------------------------------------
// Launch. Inputs: Q, K, V, mask(ignored), w_q, w_k, w_v, w_o. Out: [B,S,D] f32
// ---------------------------------------------------------------------------
extern "C" void kernel_launch(void* const* d_in, const int* in_sizes, int n_in,
                              void* d_out, int out_size)
{
    const float* Q  = (const float*)d_in[0];
    const float* K  = (const float*)d_in[1];
    const float* V  = (const float*)d_in[2];
    const float* wq = (const float*)d_in[4];
    const float* wk = (const float*)d_in[5];
    const float* wv = (const float*)d_in[6];
    const float* wo = (const float*)d_in[7];
    float* out = (float*)d_out;

    __half *hiq, *hik, *hiv, *hwq, *hwk, *hwv, *hwo, *hq, *hk, *hvt, *hao;
    cudaGetSymbolAddress((void**)&hiq, h_in_q);
    cudaGetSymbolAddress((void**)&hik, h_in_k);
    cudaGetSymbolAddress((void**)&hiv, h_in_v);
    cudaGetSymbolAddress((void**)&hwq, h_wq);
    cudaGetSymbolAddress((void**)&hwk, h_wk);
    cudaGetSymbolAddress((void**)&hwv, h_wv);
    cudaGetSymbolAddress((void**)&hwo, h_wo);
    cudaGetSymbolAddress((void**)&hq,  h_q);
    cudaGetSymbolAddress((void**)&hk,  h_k);
    cudaGetSymbolAddress((void**)&hvt, h_vt);
    cudaGetSymbolAddress((void**)&hao, h_ao);

    cudaFuncSetAttribute(gemm_h<0>, cudaFuncAttributeMaxDynamicSharedMemorySize, GSMEMH);
    cudaFuncSetAttribute(gemm_h<1>, cudaFuncAttributeMaxDynamicSharedMemorySize, GSMEMH);
    cudaFuncSetAttribute(gemm_h<2>, cudaFuncAttributeMaxDynamicSharedMemorySize, GSMEMH);
    cudaFuncSetAttribute(attn_tc, cudaFuncAttributeMaxDynamicSharedMemorySize, ASMEMH);

    const int NT4 = CB * CS * CD / 4;   // 1048576 float4 per activation
    const int NW4 = CD * CD / 4;        // 262144 float4 per weight
    cvt3<<<dim3(NT4 / 256, 3), 256>>>(Q, K, V, hiq, hik, hiv);
    cvt4<<<dim3(NW4 / 256, 4), 256>>>(wq, wk, wv, wo, hwq, hwk, hwv, hwo);

    dim3 gg(CD / BN, CM / BM);   // (4, 32) = 128 CTAs, single wave
    gemm_h<0><<<gg, 256, GSMEMH>>>(hiq, hwq, hq,  CM, CD, CD);
    gemm_h<0><<<gg, 256, GSMEMH>>>(hik, hwk, hk,  CM, CD, CD);
    gemm_h<1><<<gg, 256, GSMEMH>>>(hiv, hwv, hvt, CM, CD, CD);   // writes Vt

    attn_tc<<<dim3(CS / QT, CB * CH), 128, ASMEMH>>>(hq, hk, hvt, hao);

    gemm_h<2><<<gg, 256, GSMEMH>>>(hao, hwo, out, CM, CD, CD);
}